// round 8
// baseline (speedup 1.0000x reference)
#include <cuda_runtime.h>

// ConvQuadInterp3d over x:(2,1,8,512,512) fp32.
// Output = coords_max (B,1,3,D,H,W) then y_max (B,1,D,H,W), fp32.
// Each thread: 4 consecutive w (float4 I/O), fully-unrolled d loop.
// Per-plane compressed window: mid row M[6], dv[6]=bot-top, sv[6]=bot+top,
// NMS triple-maxes t[4]. All derivative formulas algebraically identical
// (bit-exact) to the scalar version.

#define Dd 8
#define Hh 512
#define Ww 512
#define Bb 2
#define PLANE (Hh * Ww)

__device__ __forceinline__ void load_row6(const float* __restrict__ row, int w0,
                                          bool wL, bool wR, float* v) {
    const float4 q = __ldg(reinterpret_cast<const float4*>(row + w0));
    v[1] = q.x; v[2] = q.y; v[3] = q.z; v[4] = q.w;
    v[0] = wL ? q.x : __ldg(row + w0 - 1);
    v[5] = wR ? q.w : __ldg(row + w0 + 4);
}

// Load plane dn and compress: M (mid row), dv = B - T, sv = B + T, t = NMS triples.
__device__ __forceinline__ void load_plane(const float* __restrict__ pl,
                                           int otop, int omid, int obot,
                                           int w0, bool wL, bool wR,
                                           float* M, float* dv, float* sv, float* t) {
    float T[6], B[6];
    load_row6(pl + otop, w0, wL, wR, T);
    load_row6(pl + omid, w0, wL, wR, M);
    load_row6(pl + obot, w0, wL, wR, B);
    float c[6];
#pragma unroll
    for (int i = 0; i < 6; i++) {
        c[i]  = fmaxf(T[i], fmaxf(M[i], B[i]));
        dv[i] = B[i] - T[i];
        sv[i] = B[i] + T[i];
    }
    const float p1 = fmaxf(c[1], c[2]);
    const float p3 = fmaxf(c[3], c[4]);
    t[0] = fmaxf(c[0], p1);
    t[1] = fmaxf(p1, c[3]);
    t[2] = fmaxf(c[2], p3);
    t[3] = fmaxf(p3, c[5]);
}

__global__ void __launch_bounds__(128, 5)
conv_quad_interp3d_kernel(const float* __restrict__ x, float* __restrict__ out) {
    const int w0 = (blockIdx.x * 32 + threadIdx.x) * 4;  // multiple of 4
    const int h  = blockIdx.y * 4 + threadIdx.y;
    const int b  = blockIdx.z;

    const bool wL = (w0 == 0), wR = (w0 == Ww - 4);
    const int hm = max(h - 1, 0), hp = min(h + 1, Hh - 1);
    const int otop = hm * Ww, omid = h * Ww, obot = hp * Ww;
    const float hf = (float)h;
    const float wf = (float)w0;

    const float* xb = x + b * Dd * PLANE;

    // Window: P (prev, no sv), C (center), N (next)
    float MP[6], dvP[6], tP[4];
    float MC[6], dvC[6], svC[6], tC[4];
    float MN[6], dvN[6], svN[6], tN[4];

    load_plane(xb + 0 * PLANE, otop, omid, obot, w0, wL, wR, MC, dvC, svC, tC);
#pragma unroll
    for (int i = 0; i < 6; i++) { MP[i] = MC[i]; dvP[i] = dvC[i]; }
#pragma unroll
    for (int i = 0; i < 4; i++) tP[i] = tC[i];     // replicate pad d = -1
    load_plane(xb + 1 * PLANE, otop, omid, obot, w0, wL, wR, MN, dvN, svN, tN);

    const int hw = h * Ww + w0;
    float* pD = out + (b * 3 + 0) * Dd * PLANE + hw;
    float* pW = pD + Dd * PLANE;
    float* pH = pW + Dd * PLANE;
    float* pY = out + (Bb * 3) * Dd * PLANE + b * Dd * PLANE + hw;

#pragma unroll
    for (int d = 0; d < Dd; d++) {
        float rD[4], rW[4], rH[4], rY[4];

#pragma unroll
        for (int j = 0; j < 4; j++) {
            const float c = MC[j + 1];

            // NMS: max over 27 = max of 3 cached per-plane triple-maxes.
            const float m = fmaxf(tP[j], fmaxf(tC[j], tN[j]));
            const bool nms = (c == m);

            // Gradients (central diff / 2, replicate pad)
            const float gx = 0.5f * (MC[j + 2] - MC[j]);
            const float gy = 0.5f * dvC[j + 1];
            const float gs = 0.5f * (MN[j + 1] - MP[j + 1]);

            // Hessian (cross terms * 0.25)
            const float axx = MC[j] + MC[j + 2] - 2.0f * c;
            const float ayy = svC[j + 1] - 2.0f * c;
            const float ass = MP[j + 1] + MN[j + 1] - 2.0f * c;
            const float axy = 0.25f * (dvC[j + 2] - dvC[j]);
            const float ays = 0.25f * (dvN[j + 1] - dvP[j + 1]);
            const float axs = 0.25f * ((MN[j + 2] - MP[j + 2]) - (MN[j] - MP[j]));

            // Symmetric 3x3 solve via adjugate (Cramer)
            const float c00 = ayy * ass - ays * ays;
            const float c01 = axs * ays - axy * ass;
            const float c02 = axy * ays - axs * ayy;
            const float det = axx * c00 + axy * c01 + axs * c02;
            const bool keep = nms && (det != 0.0f);

            float rx = 0.0f, ry = 0.0f, rs = 0.0f;
            if (keep) {
                const float inv = 1.0f / det;
                const float c11 = axx * ass - axs * axs;
                const float c12 = axy * axs - axx * ays;
                const float c22 = axx * ayy - axy * axy;
                rx = -(c00 * gx + c01 * gy + c02 * gs) * inv;
                ry = -(c01 * gx + c11 * gy + c12 * gs) * inv;
                rs = -(c02 * gx + c12 * gy + c22 * gs) * inv;
                const float big = fmaxf(fabsf(rx), fmaxf(fabsf(ry), fabsf(rs)));
                if (big > 0.7f) { rx = 0.0f; ry = 0.0f; rs = 0.0f; }
            }

            const float dyv = 0.5f * (gx * rx + gy * ry + gs * rs);
            rY[j] = c + dyv + (keep ? 10.0f : 0.0f);
            // grid channels (d, w, h) + flipped refinement (s, y, x)
            rD[j] = (float)d + rs;
            rW[j] = (wf + (float)j) + ry;
            rH[j] = hf + rx;
        }

        *reinterpret_cast<float4*>(pD + d * PLANE) = make_float4(rD[0], rD[1], rD[2], rD[3]);
        *reinterpret_cast<float4*>(pW + d * PLANE) = make_float4(rW[0], rW[1], rW[2], rW[3]);
        *reinterpret_cast<float4*>(pH + d * PLANE) = make_float4(rH[0], rH[1], rH[2], rH[3]);
        *reinterpret_cast<float4*>(pY + d * PLANE) = make_float4(rY[0], rY[1], rY[2], rY[3]);

        if (d < Dd - 1) {
            // Shift window (free renames in the unrolled loop)
#pragma unroll
            for (int i = 0; i < 6; i++) {
                MP[i] = MC[i]; dvP[i] = dvC[i];
                MC[i] = MN[i]; dvC[i] = dvN[i]; svC[i] = svN[i];
            }
#pragma unroll
            for (int i = 0; i < 4; i++) { tP[i] = tC[i]; tC[i] = tN[i]; }
            if (d + 2 < Dd) {
                load_plane(xb + (d + 2) * PLANE, otop, omid, obot, w0, wL, wR,
                           MN, dvN, svN, tN);
            }
            // else: N keeps plane 7's values == replicate pad at d = 8 (MN/dvN/svN/tN
            // already hold plane 7 after the shift at d == 6).
        }
    }
}

extern "C" void kernel_launch(void* const* d_in, const int* in_sizes, int n_in,
                              void* d_out, int out_size) {
    const float* x = (const float*)d_in[0];
    float* out = (float*)d_out;
    dim3 block(32, 4, 1);
    dim3 grid(Ww / (32 * 4), Hh / 4, Bb);  // (4, 128, 2)
    conv_quad_interp3d_kernel<<<grid, block>>>(x, out);
}

// round 10
// speedup vs baseline: 1.3131x; 1.3131x over previous
#include <cuda_runtime.h>

// ConvQuadInterp3d over x:(2,1,8,512,512) fp32.
// Output = coords_max (B,1,3,D,H,W) then y_max (B,1,D,H,W), fp32.
// One thread per (b,h,w); fully-unrolled d loop; rolling 3-plane window where
// NMS uses one cached whole-plane 3x3 max per plane (3 scalars) and the prev
// plane keeps only its 5 cross values. Minimal register state -> 8 blocks/SM.

#define Dd 8
#define Hh 512
#define Ww 512
#define Bb 2
#define PLANE (Hh * Ww)

// Load 3x3 neighborhood of (h,w) in plane `base`, return whole-plane 3x3 max.
__device__ __forceinline__ float load_plane(const float* __restrict__ x, int base,
                                            int hm, int h0, int hp,
                                            int wm, int w0, int wp, float* p) {
    const float* r0 = x + base + hm * Ww;
    const float* r1 = x + base + h0 * Ww;
    const float* r2 = x + base + hp * Ww;
    p[0] = __ldg(r0 + wm); p[1] = __ldg(r0 + w0); p[2] = __ldg(r0 + wp);
    p[3] = __ldg(r1 + wm); p[4] = __ldg(r1 + w0); p[5] = __ldg(r1 + wp);
    p[6] = __ldg(r2 + wm); p[7] = __ldg(r2 + w0); p[8] = __ldg(r2 + wp);
    float m0 = fmaxf(p[0], fmaxf(p[3], p[6]));
    float m1 = fmaxf(p[1], fmaxf(p[4], p[7]));
    float m2 = fmaxf(p[2], fmaxf(p[5], p[8]));
    return fmaxf(m0, fmaxf(m1, m2));
}

__global__ void __launch_bounds__(128, 8)
conv_quad_interp3d_kernel(const float* __restrict__ x, float* __restrict__ out) {
    const int w = blockIdx.x * 32 + threadIdx.x;
    const int h = blockIdx.y * 4 + threadIdx.y;
    const int b = blockIdx.z;

    const int wm = max(w - 1, 0), wp = min(w + 1, Ww - 1);
    const int hm = max(h - 1, 0), hp = min(h + 1, Hh - 1);
    const int xbase = b * Dd * PLANE;
    const float wf = (float)w, hf = (float)h;

    // Window: prev plane = 5 cross values + plane max; C/N = full 9 + plane max.
    float pm1, pm3, pm4, pm5, pm7, mP;
    float C[9], N[9], mC, mN;

    mC = load_plane(x, xbase + 0 * PLANE, hm, h, hp, wm, w, wp, C);
    pm1 = C[1]; pm3 = C[3]; pm4 = C[4]; pm5 = C[5]; pm7 = C[7];  // replicate d=-1
    mP = mC;
    mN = load_plane(x, xbase + 1 * PLANE, hm, h, hp, wm, w, wp, N);

    const int hw = h * Ww + w;
    float* pD = out + (b * 3 + 0) * Dd * PLANE + hw;
    float* pW = out + (b * 3 + 1) * Dd * PLANE + hw;
    float* pH = out + (b * 3 + 2) * Dd * PLANE + hw;
    float* pY = out + (Bb * 3) * Dd * PLANE + b * Dd * PLANE + hw;

#pragma unroll
    for (int d = 0; d < Dd; d++) {
        const float c = C[4];

        // NMS: max over 27 = max of the 3 cached whole-plane maxima.
        const float m = fmaxf(mP, fmaxf(mC, mN));
        const bool nms = (c == m);

        // Gradients (central diff / 2, replicate pad)
        const float gx = 0.5f * (C[5] - C[3]);
        const float gy = 0.5f * (C[7] - C[1]);
        const float gs = 0.5f * (N[4] - pm4);

        // Hessian (cross terms * 0.25 per reference)
        const float axx = C[3] + C[5] - 2.0f * c;
        const float ayy = C[1] + C[7] - 2.0f * c;
        const float ass = pm4 + N[4] - 2.0f * c;
        const float axy = 0.25f * (C[0] + C[8] - C[6] - C[2]);
        const float ays = 0.25f * (pm1 + N[7] - N[1] - pm7);
        const float axs = 0.25f * (pm3 + N[5] - N[3] - pm5);

        // Symmetric 3x3 solve via adjugate (Cramer)
        const float c00 = ayy * ass - ays * ays;
        const float c01 = axs * ays - axy * ass;
        const float c02 = axy * ays - axs * ayy;
        const float det = axx * c00 + axy * c01 + axs * c02;
        const bool keep = nms && (det != 0.0f);

        float rx = 0.0f, ry = 0.0f, rs = 0.0f;
        if (keep) {
            const float inv = 1.0f / det;
            const float c11 = axx * ass - axs * axs;
            const float c12 = axy * axs - axx * ays;
            const float c22 = axx * ayy - axy * axy;
            rx = -(c00 * gx + c01 * gy + c02 * gs) * inv;
            ry = -(c01 * gx + c11 * gy + c12 * gs) * inv;
            rs = -(c02 * gx + c12 * gy + c22 * gs) * inv;
            const float big = fmaxf(fabsf(rx), fmaxf(fabsf(ry), fabsf(rs)));
            if (big > 0.7f) { rx = 0.0f; ry = 0.0f; rs = 0.0f; }
        }

        const float dyv = 0.5f * (gx * rx + gy * ry + gs * rs);
        const float y = c + dyv + (keep ? 10.0f : 0.0f);

        // coords channels: grid(d, w, h) + flipped refinement (s, y, x)
        pD[d * PLANE] = (float)d + rs;
        pW[d * PLANE] = wf + ry;
        pH[d * PLANE] = hf + rx;
        pY[d * PLANE] = y;

        if (d < Dd - 1) {
            pm1 = C[1]; pm3 = C[3]; pm4 = C[4]; pm5 = C[5]; pm7 = C[7];
            mP = mC;
#pragma unroll
            for (int i = 0; i < 9; i++) C[i] = N[i];
            mC = mN;
            if (d + 2 < Dd) {
                mN = load_plane(x, xbase + (d + 2) * PLANE, hm, h, hp, wm, w, wp, N);
            }
            // else: N and mN keep plane 7 == replicate pad at d = 8.
        }
    }
}

extern "C" void kernel_launch(void* const* d_in, const int* in_sizes, int n_in,
                              void* d_out, int out_size) {
    const float* x = (const float*)d_in[0];
    float* out = (float*)d_out;
    dim3 block(32, 4, 1);
    dim3 grid(Ww / 32, Hh / 4, Bb);  // (16, 128, 2)
    conv_quad_interp3d_kernel<<<grid, block>>>(x, out);
}

// round 12
// speedup vs baseline: 1.3368x; 1.0180x over previous
#include <cuda_runtime.h>

// ConvQuadInterp3d over x:(2,1,8,512,512) fp32.
// Output = coords_max (B,1,3,D,H,W) then y_max (B,1,D,H,W), fp32.
// Block = 32x4 tile. Planes staged through double-buffered SMEM (6x34 halo,
// 204 floats): 2 coalesced LDG/thread with precomputed clamped offsets, one
// sync per d-iteration, LDG for plane d+3 issued a full iteration before its
// STS. Window reads are LDS (29 cyc) instead of L2 (~240 cyc).

#define Dd 8
#define Hh 512
#define Ww 512
#define Bb 2
#define PLANE (Hh * Ww)
#define TW 32
#define TH 4
#define SP 34
#define SELEMS (6 * SP)   // 204

__device__ __forceinline__ float max9(const float* P) {
    float m = fmaxf(fmaxf(fmaxf(P[0], P[1]), fmaxf(P[2], P[3])),
                    fmaxf(fmaxf(P[4], P[5]), fmaxf(P[6], P[7])));
    return fmaxf(m, P[8]);
}

__global__ void __launch_bounds__(128, 7)
conv_quad_interp3d_kernel(const float* __restrict__ x, float* __restrict__ out) {
    __shared__ float sb[2][SELEMS];

    const int tdx = threadIdx.x, tdy = threadIdx.y;
    const int tid = tdy * TW + tdx;
    const int w0 = blockIdx.x * TW, h0 = blockIdx.y * TH;
    const int b = blockIdx.z;
    const int w = w0 + tdx, h = h0 + tdy;

    // Cooperative-load mapping: elements e0, e1 of the 6x34 halo tile; global
    // offsets clamped (replicate pad) once — in-loop loads are [reg + plane*imm].
    const int e0 = tid, e1 = tid + 128;
    const bool has1 = (e1 < SELEMS);
    const int goff0 = min(max(h0 - 1 + e0 / SP, 0), Hh - 1) * Ww
                    + min(max(w0 - 1 + e0 % SP, 0), Ww - 1);
    const int goff1 = min(max(h0 - 1 + e1 / SP, 0), Hh - 1) * Ww
                    + min(max(w0 - 1 + e1 % SP, 0), Ww - 1);

    const float* xb = x + b * Dd * PLANE;
    const int sbase = tdy * SP + tdx;  // thread's 3x3 window top-left in the tile

#define READ9(P, buf) do {                                                      \
    P[0] = sb[buf][sbase];          P[1] = sb[buf][sbase + 1];                  \
    P[2] = sb[buf][sbase + 2];      P[3] = sb[buf][sbase + SP];                 \
    P[4] = sb[buf][sbase + SP + 1]; P[5] = sb[buf][sbase + SP + 2];             \
    P[6] = sb[buf][sbase + 2*SP];   P[7] = sb[buf][sbase + 2*SP + 1];           \
    P[8] = sb[buf][sbase + 2*SP + 2];                                           \
} while (0)

    // ---- Prologue: planes 0 and 1 (overlapped LDG), then prefetch plane 2.
    float sA0, sA1, sB0, sB1;
    sA0 = __ldg(xb + goff0);          sA1 = has1 ? __ldg(xb + goff1) : 0.0f;
    sB0 = __ldg(xb + PLANE + goff0);  sB1 = has1 ? __ldg(xb + PLANE + goff1) : 0.0f;

    sb[0][e0] = sA0; if (has1) sb[0][e1] = sA1;
    __syncthreads();
    float C[9], N[9];
    READ9(C, 0);
    float mC = max9(C);
    float pm1 = C[1], pm3 = C[3], pm4 = C[4], pm5 = C[5], pm7 = C[7];
    float mP = mC;                                        // replicate pad d = -1

    sb[1][e0] = sB0; if (has1) sb[1][e1] = sB1;
    __syncthreads();
    READ9(N, 1);
    float mN = max9(N);

    sA0 = __ldg(xb + 2 * PLANE + goff0);                  // prefetch plane 2
    if (has1) sA1 = __ldg(xb + 2 * PLANE + goff1);

    const float wf = (float)w, hf = (float)h;
    const int hw = h * Ww + w;
    float* pD = out + (b * 3 + 0) * Dd * PLANE + hw;
    float* pW = out + (b * 3 + 1) * Dd * PLANE + hw;
    float* pH = out + (b * 3 + 2) * Dd * PLANE + hw;
    float* pY = out + (Bb * 3) * Dd * PLANE + b * Dd * PLANE + hw;

#pragma unroll
    for (int d = 0; d < Dd; d++) {
        const float c = C[4];

        // NMS: max over 27 = max of the 3 cached whole-plane 3x3 maxima.
        const float m = fmaxf(mP, fmaxf(mC, mN));
        const bool nms = (c == m);

        // Gradients (central diff / 2, replicate pad)
        const float gx = 0.5f * (C[5] - C[3]);
        const float gy = 0.5f * (C[7] - C[1]);
        const float gs = 0.5f * (N[4] - pm4);

        // Hessian (cross terms * 0.25 per reference)
        const float axx = C[3] + C[5] - 2.0f * c;
        const float ayy = C[1] + C[7] - 2.0f * c;
        const float ass = pm4 + N[4] - 2.0f * c;
        const float axy = 0.25f * (C[0] + C[8] - C[6] - C[2]);
        const float ays = 0.25f * (pm1 + N[7] - N[1] - pm7);
        const float axs = 0.25f * (pm3 + N[5] - N[3] - pm5);

        // Symmetric 3x3 solve via adjugate (Cramer)
        const float c00 = ayy * ass - ays * ays;
        const float c01 = axs * ays - axy * ass;
        const float c02 = axy * ays - axs * ayy;
        const float det = axx * c00 + axy * c01 + axs * c02;
        const bool keep = nms && (det != 0.0f);

        float rx = 0.0f, ry = 0.0f, rs = 0.0f;
        if (keep) {
            const float inv = 1.0f / det;
            const float c11 = axx * ass - axs * axs;
            const float c12 = axy * axs - axx * ays;
            const float c22 = axx * ayy - axy * axy;
            rx = -(c00 * gx + c01 * gy + c02 * gs) * inv;
            ry = -(c01 * gx + c11 * gy + c12 * gs) * inv;
            rs = -(c02 * gx + c12 * gy + c22 * gs) * inv;
            const float big = fmaxf(fabsf(rx), fmaxf(fabsf(ry), fabsf(rs)));
            if (big > 0.7f) { rx = 0.0f; ry = 0.0f; rs = 0.0f; }
        }

        const float dyv = 0.5f * (gx * rx + gy * ry + gs * rs);
        const float y = c + dyv + (keep ? 10.0f : 0.0f);

        // coords channels: grid(d, w, h) + flipped refinement (s, y, x)
        pD[d * PLANE] = (float)d + rs;
        pW[d * PLANE] = wf + ry;
        pH[d * PLANE] = hf + rx;
        pY[d * PLANE] = y;

        if (d < Dd - 1) {
            pm1 = C[1]; pm3 = C[3]; pm4 = C[4]; pm5 = C[5]; pm7 = C[7];
            mP = mC;
#pragma unroll
            for (int i = 0; i < 9; i++) C[i] = N[i];
            mC = mN;
            if (d < Dd - 2) {
                // Commit staged plane d+2 to smem, sync, read it into N.
                sb[d & 1][e0] = sA0; if (has1) sb[d & 1][e1] = sA1;
                __syncthreads();
                READ9(N, d & 1);
                mN = max9(N);
                // Issue LDG for plane d+3 — consumed one iteration later.
                if (d < Dd - 3) {
                    sA0 = __ldg(xb + (d + 3) * PLANE + goff0);
                    if (has1) sA1 = __ldg(xb + (d + 3) * PLANE + goff1);
                }
            }
            // else: N and mN keep plane 7 == replicate pad at d = 8.
        }
    }
}

extern "C" void kernel_launch(void* const* d_in, const int* in_sizes, int n_in,
                              void* d_out, int out_size) {
    const float* x = (const float*)d_in[0];
    float* out = (float*)d_out;
    dim3 block(TW, TH, 1);
    dim3 grid(Ww / TW, Hh / TH, Bb);  // (16, 128, 2)
    conv_quad_interp3d_kernel<<<grid, block>>>(x, out);
}